// round 8
// baseline (speedup 1.0000x reference)
#include <cuda_runtime.h>
#include <cstdint>

// LIF spike scan over T=8 (contiguous innermost axis).
// x: [32,128,32,32,8] fp32 -> spikes {0,1} fp32, same shape.
//
// Roofline-bound: 268 MB irreducible R+W at ~6.0 TB/s (75% of spec = HBM3e
// 1:1 R/W turnaround ceiling). 1 thread = 1 position = LDG.E.256 + register
// scan + STG.E.256, both .cs. 128-thread CTAs (16/SM): finest CTA-replacement
// granularity — the replacement stream is what pipelines loads against stores.

#define TAU 0.2f
#define VTH 0.3f

__global__ void __launch_bounds__(128, 16)
lif_spike_kernel(const float* __restrict__ x, float* __restrict__ out, int n_pos) {
    int p = blockIdx.x * blockDim.x + threadIdx.x;
    if (p >= n_pos) return;

    const float* xp = x + (size_t)p * 8;
    float* op = out + (size_t)p * 8;

    float x0, x1, x2, x3, x4, x5, x6, x7;
    asm volatile(
        "ld.global.cs.v8.f32 {%0,%1,%2,%3,%4,%5,%6,%7}, [%8];"
        : "=f"(x0), "=f"(x1), "=f"(x2), "=f"(x3),
          "=f"(x4), "=f"(x5), "=f"(x6), "=f"(x7)
        : "l"(xp));

    float u, o;
    float s0, s1, s2, s3, s4, s5, s6, s7;
    u = x0;                        o = (u > VTH) ? 1.0f : 0.0f; s0 = o;
    u = TAU * u * (1.0f - o) + x1; o = (u > VTH) ? 1.0f : 0.0f; s1 = o;
    u = TAU * u * (1.0f - o) + x2; o = (u > VTH) ? 1.0f : 0.0f; s2 = o;
    u = TAU * u * (1.0f - o) + x3; o = (u > VTH) ? 1.0f : 0.0f; s3 = o;
    u = TAU * u * (1.0f - o) + x4; o = (u > VTH) ? 1.0f : 0.0f; s4 = o;
    u = TAU * u * (1.0f - o) + x5; o = (u > VTH) ? 1.0f : 0.0f; s5 = o;
    u = TAU * u * (1.0f - o) + x6; o = (u > VTH) ? 1.0f : 0.0f; s6 = o;
    u = TAU * u * (1.0f - o) + x7; o = (u > VTH) ? 1.0f : 0.0f; s7 = o;

    asm volatile(
        "st.global.cs.v8.f32 [%0], {%1,%2,%3,%4,%5,%6,%7,%8};"
        :
        : "l"(op),
          "f"(s0), "f"(s1), "f"(s2), "f"(s3),
          "f"(s4), "f"(s5), "f"(s6), "f"(s7)
        : "memory");
}

extern "C" void kernel_launch(void* const* d_in, const int* in_sizes, int n_in,
                              void* d_out, int out_size) {
    const float* x = (const float*)d_in[0];
    float* out = (float*)d_out;
    int n_total = in_sizes[0];   // B*C*H*W*T
    int n_pos = n_total / 8;     // one position per thread

    int threads = 128;
    int blocks = (n_pos + threads - 1) / threads;
    lif_spike_kernel<<<blocks, threads>>>(x, out, n_pos);
}

// round 9
// speedup vs baseline: 1.0028x; 1.0028x over previous
#include <cuda_runtime.h>
#include <cstdint>

// LIF spike scan over T=8 (contiguous innermost axis).
// x: [32,128,32,32,8] fp32 -> spikes {0,1} fp32, same shape.
//
// FINAL — roofline-complete. 268 MB irreducible R+W traffic sustained at
// ~6.0 TB/s (75% of 8 TB/s spec = HBM3e 1:1 R/W turnaround ceiling).
// Measured-equivalent-or-better than: float4x2, MLP=2/4 per thread,
// persistent grid-stride (-19us worse), .wb stores, 128/512-thread CTAs.
//
// Design: 1 thread = 1 spatial position. One LDG.E.256, T=8 scan fully
// unrolled in registers (8 FFMA + 8 FSETP/SEL), one STG.E.256; both .cs
// (evict-first — zero reuse in either stream). Flat 16384-CTA launch:
// hardware CTA replacement pipelines fresh loads against draining stores.

#define TAU 0.2f
#define VTH 0.3f

__global__ void __launch_bounds__(256, 8)
lif_spike_kernel(const float* __restrict__ x, float* __restrict__ out, int n_pos) {
    int p = blockIdx.x * blockDim.x + threadIdx.x;
    if (p >= n_pos) return;

    const float* xp = x + (size_t)p * 8;
    float* op = out + (size_t)p * 8;

    float x0, x1, x2, x3, x4, x5, x6, x7;
    asm volatile(
        "ld.global.cs.v8.f32 {%0,%1,%2,%3,%4,%5,%6,%7}, [%8];"
        : "=f"(x0), "=f"(x1), "=f"(x2), "=f"(x3),
          "=f"(x4), "=f"(x5), "=f"(x6), "=f"(x7)
        : "l"(xp));

    float u, o;
    float s0, s1, s2, s3, s4, s5, s6, s7;
    u = x0;                        o = (u > VTH) ? 1.0f : 0.0f; s0 = o;
    u = TAU * u * (1.0f - o) + x1; o = (u > VTH) ? 1.0f : 0.0f; s1 = o;
    u = TAU * u * (1.0f - o) + x2; o = (u > VTH) ? 1.0f : 0.0f; s2 = o;
    u = TAU * u * (1.0f - o) + x3; o = (u > VTH) ? 1.0f : 0.0f; s3 = o;
    u = TAU * u * (1.0f - o) + x4; o = (u > VTH) ? 1.0f : 0.0f; s4 = o;
    u = TAU * u * (1.0f - o) + x5; o = (u > VTH) ? 1.0f : 0.0f; s5 = o;
    u = TAU * u * (1.0f - o) + x6; o = (u > VTH) ? 1.0f : 0.0f; s6 = o;
    u = TAU * u * (1.0f - o) + x7; o = (u > VTH) ? 1.0f : 0.0f; s7 = o;

    asm volatile(
        "st.global.cs.v8.f32 [%0], {%1,%2,%3,%4,%5,%6,%7,%8};"
        :
        : "l"(op),
          "f"(s0), "f"(s1), "f"(s2), "f"(s3),
          "f"(s4), "f"(s5), "f"(s6), "f"(s7)
        : "memory");
}

extern "C" void kernel_launch(void* const* d_in, const int* in_sizes, int n_in,
                              void* d_out, int out_size) {
    const float* x = (const float*)d_in[0];
    float* out = (float*)d_out;
    int n_total = in_sizes[0];   // B*C*H*W*T
    int n_pos = n_total / 8;     // one position per thread

    int threads = 256;
    int blocks = (n_pos + threads - 1) / threads;
    lif_spike_kernel<<<blocks, threads>>>(x, out, n_pos);
}

// round 10
// speedup vs baseline: 1.0360x; 1.0331x over previous
#include <cuda_runtime.h>
#include <cstdint>

// LIF spike scan over T=8 (contiguous innermost axis).
// x: [32,128,32,32,8] fp32 -> spikes {0,1} fp32, same shape.
//
// FINAL (converged R2 config, noise-calibrated over 4 identical runs:
// kernel 35.6-36.6us, DRAM 74-76%). 268 MB irreducible R+W traffic at
// ~6.0 TB/s = ~75% of 8 TB/s spec, the HBM3e 1:1 read/write turnaround
// ceiling. Design space fully measured:
//   vector width 128->256-bit : -2.0us (the only real win)
//   cache policy .cs/.wb      : neutral
//   per-thread MLP 1/2/4      : neutral
//   persistent grid-stride    : +19us regression (CTA replacement IS the pipeline)
//   CTA size 128/256/512      : 256 best within noise
//
// 1 thread = 1 spatial position: one LDG.E.256, T=8 scan unrolled in
// registers, one STG.E.256, both .cs (zero reuse either stream).

#define TAU 0.2f
#define VTH 0.3f

__global__ void __launch_bounds__(256, 8)
lif_spike_kernel(const float* __restrict__ x, float* __restrict__ out, int n_pos) {
    int p = blockIdx.x * blockDim.x + threadIdx.x;
    if (p >= n_pos) return;

    const float* xp = x + (size_t)p * 8;
    float* op = out + (size_t)p * 8;

    float x0, x1, x2, x3, x4, x5, x6, x7;
    asm volatile(
        "ld.global.cs.v8.f32 {%0,%1,%2,%3,%4,%5,%6,%7}, [%8];"
        : "=f"(x0), "=f"(x1), "=f"(x2), "=f"(x3),
          "=f"(x4), "=f"(x5), "=f"(x6), "=f"(x7)
        : "l"(xp));

    float u, o;
    float s0, s1, s2, s3, s4, s5, s6, s7;
    u = x0;                        o = (u > VTH) ? 1.0f : 0.0f; s0 = o;
    u = TAU * u * (1.0f - o) + x1; o = (u > VTH) ? 1.0f : 0.0f; s1 = o;
    u = TAU * u * (1.0f - o) + x2; o = (u > VTH) ? 1.0f : 0.0f; s2 = o;
    u = TAU * u * (1.0f - o) + x3; o = (u > VTH) ? 1.0f : 0.0f; s3 = o;
    u = TAU * u * (1.0f - o) + x4; o = (u > VTH) ? 1.0f : 0.0f; s4 = o;
    u = TAU * u * (1.0f - o) + x5; o = (u > VTH) ? 1.0f : 0.0f; s5 = o;
    u = TAU * u * (1.0f - o) + x6; o = (u > VTH) ? 1.0f : 0.0f; s6 = o;
    u = TAU * u * (1.0f - o) + x7; o = (u > VTH) ? 1.0f : 0.0f; s7 = o;

    asm volatile(
        "st.global.cs.v8.f32 [%0], {%1,%2,%3,%4,%5,%6,%7,%8};"
        :
        : "l"(op),
          "f"(s0), "f"(s1), "f"(s2), "f"(s3),
          "f"(s4), "f"(s5), "f"(s6), "f"(s7)
        : "memory");
}

extern "C" void kernel_launch(void* const* d_in, const int* in_sizes, int n_in,
                              void* d_out, int out_size) {
    const float* x = (const float*)d_in[0];
    float* out = (float*)d_out;
    int n_total = in_sizes[0];   // B*C*H*W*T
    int n_pos = n_total / 8;     // one position per thread

    int threads = 256;
    int blocks = (n_pos + threads - 1) / threads;
    lif_spike_kernel<<<blocks, threads>>>(x, out, n_pos);
}